// round 9
// baseline (speedup 1.0000x reference)
#include <cuda_runtime.h>

#define BB 8
#define NQV 4096
#define NKV 4096
#define CC 256
#define KNN 16
#define HH 32
#define EPSV 1e-5f
#define FINF 3.402823466e38f
#define CAP 160
// Morton sort grid (locality only -- correctness independent of mapping)
#define GRM 16
#define NCELLM (GRM * GRM * GRM)

// Scratch (device globals: allocation-free rule)
__device__ float    g_kvproj[BB * NKV * HH];   // s1 * (kv_feat @ w1a^T)
__device__ float    g_qterm [BB * NQV * HH];   // s1 * (q_feat @ (w1b-w1a)^T) + t1
__device__ unsigned g_topk  [BB * NQV * KNN];  // neighbor indices (unordered set)
// Morton counting sort
__device__ unsigned g_cnt   [BB * NCELLM];
__device__ unsigned g_qcnt  [BB * NCELLM];
__device__ unsigned g_coff  [BB * NCELLM];
__device__ unsigned g_qoff  [BB * NCELLM];
__device__ unsigned short g_cellid [BB * NKV];
__device__ unsigned short g_qcellid[BB * NQV];
__device__ float4   g_spts  [BB * NKV];   // Morton-sorted kv {x,y,z,|k|^2}
__device__ unsigned g_sidx  [BB * NKV];   // sorted pos -> original kv index
__device__ float4   g_qpts  [BB * NQV];   // Morton-sorted queries
__device__ unsigned g_qidx  [BB * NQV];   // sorted pos -> original q index

__device__ __forceinline__ int mcell_of(float x) {
    int c = (int)floorf((x + 4.0f) * 2.0f);
    return min(GRM - 1, max(0, c));
}
__device__ __forceinline__ unsigned spread4(unsigned x) {
    return (x & 1u) | ((x & 2u) << 2) | ((x & 4u) << 4) | ((x & 8u) << 6);
}
__device__ __forceinline__ unsigned morton(int cx, int cy, int cz) {
    return spread4((unsigned)cx) | (spread4((unsigned)cy) << 1) | (spread4((unsigned)cz) << 2);
}

// ---------------------------------------------------------------------------
// Morton counting-sort build (machinery validated in R6; re-keyed)
// ---------------------------------------------------------------------------
__global__ void zero_kernel() {
    const int i = blockIdx.x * 256 + threadIdx.x;
    if (i < BB * NCELLM) { g_cnt[i] = 0; g_qcnt[i] = 0; }
}

__global__ void bin_kernel(const float* __restrict__ kxyz,
                           const float* __restrict__ qxyz) {
    const int gi  = blockIdx.x * 512 + threadIdx.x;   // 128 x 512 = 65536
    const int isq = gi >> 15;
    const int i   = gi & 32767;
    const int b   = i >> 12;
    const float* xyz = isq ? qxyz : kxyz;
    const float x = xyz[(size_t)i * 3 + 0];
    const float y = xyz[(size_t)i * 3 + 1];
    const float z = xyz[(size_t)i * 3 + 2];
    const unsigned cid = morton(mcell_of(x), mcell_of(y), mcell_of(z));
    if (isq) {
        g_qcellid[i] = (unsigned short)cid;
        atomicAdd(&g_qcnt[b * NCELLM + cid], 1u);
    } else {
        g_cellid[i] = (unsigned short)cid;
        atomicAdd(&g_cnt[b * NCELLM + cid], 1u);
    }
}

// 16 blocks: blockIdx.x = b*2 + isq. 1024 threads x 4 cells, warp-scan.
__global__ __launch_bounds__(1024) void scan_kernel() {
    __shared__ unsigned wsum[32];
    const int isq = blockIdx.x & 1;
    const int b   = blockIdx.x >> 1;
    const int tid = threadIdx.x, lane = tid & 31, warp = tid >> 5;
    const unsigned* cnt = (isq ? g_qcnt : g_cnt) + b * NCELLM;
    const int base = tid * 4;
    unsigned loc[4], sum = 0;
#pragma unroll
    for (int j = 0; j < 4; ++j) {
        const unsigned v = cnt[base + j];
        loc[j] = sum;
        sum += v;
    }
    unsigned incl = sum;
#pragma unroll
    for (int off = 1; off < 32; off <<= 1) {
        const unsigned v = __shfl_up_sync(0xFFFFFFFFu, incl, off);
        if (lane >= off) incl += v;
    }
    if (lane == 31) wsum[warp] = incl;
    __syncthreads();
    if (warp == 0) {
        unsigned w = wsum[lane];
        unsigned wi = w;
#pragma unroll
        for (int off = 1; off < 32; off <<= 1) {
            const unsigned v = __shfl_up_sync(0xFFFFFFFFu, wi, off);
            if (lane >= off) wi += v;
        }
        wsum[lane] = wi - w;   // exclusive
    }
    __syncthreads();
    const unsigned tpre = wsum[warp] + (incl - sum);
    unsigned* off_arr = (isq ? g_qoff : g_coff) + b * NCELLM;
#pragma unroll
    for (int j = 0; j < 4; ++j) off_arr[base + j] = tpre + loc[j];
}

__global__ void scatter_kernel(const float* __restrict__ kxyz,
                               const float* __restrict__ qxyz) {
    const int gi  = blockIdx.x * 512 + threadIdx.x;
    const int isq = gi >> 15;
    const int i   = gi & 32767;
    const int b   = i >> 12;
    const int k   = i & (NKV - 1);
    const float* xyz = isq ? qxyz : kxyz;
    const float x = xyz[(size_t)i * 3 + 0];
    const float y = xyz[(size_t)i * 3 + 1];
    const float z = xyz[(size_t)i * 3 + 2];
    const float n2 = x * x + y * y + z * z;
    if (isq) {
        const int cid = g_qcellid[i];
        const unsigned pos = atomicAdd(&g_qoff[b * NCELLM + cid], 1u);
        g_qpts[(size_t)b * NQV + pos] = make_float4(x, y, z, n2);
        g_qidx[(size_t)b * NQV + pos] = (unsigned)k;
    } else {
        const int cid = g_cellid[i];
        const unsigned pos = atomicAdd(&g_coff[b * NCELLM + cid], 1u);
        g_spts[(size_t)b * NKV + pos] = make_float4(x, y, z, n2);
        g_sidx[(size_t)b * NKV + pos] = (unsigned)k;
    }
}

// ---------------------------------------------------------------------------
// Kernel B: exact top-16 NN. One thread per MORTON-SORTED query, full
// 4096-candidate Morton-ordered stream. Warp lanes = 32 spatially adjacent
// queries; their insert-fires cluster in the same stream segments, so the
// divergent-branch union collapses. Parallel sorted insert (dep depth 2);
// per-thread smem ring collects fired indices (superset of final 16);
// emission filters against exact tau, mapping sorted->original ids.
// ---------------------------------------------------------------------------
extern "C" __global__ __launch_bounds__(256) void topk_kernel()
{
    extern __shared__ char smem_raw[];
    float4*         s_pts = (float4*)smem_raw;                   // 64KB
    unsigned short* s_buf = (unsigned short*)(smem_raw + 65536); // CAP*256*2 = 80KB

    const int tid  = threadIdx.x;
    const int b    = blockIdx.x >> 4;               // 16 blocks per batch
    const int slot = (blockIdx.x & 15) * 256 + tid; // sorted query slot

    // Stage sorted points (coalesced float4)
    const float4* gp = g_spts + (size_t)b * NKV;
    for (int i = tid; i < NKV; i += 256) s_pts[i] = gp[i];
    __syncthreads();

    const float4 qp = g_qpts[(size_t)b * NQV + slot];
    const float ax = -2.0f * qp.x, ay = -2.0f * qp.y, az = -2.0f * qp.z;
    // ranking key d = |k|^2 - 2 q.k  (per-query constant |q|^2 dropped: exact)

    float s[16];
#pragma unroll
    for (int j = 0; j < 16; ++j) s[j] = FINF;
    int cnt = 0;

    for (int t = 0; t < NKV; t += 8) {
        float d[8];
#pragma unroll
        for (int u = 0; u < 8; ++u) {
            const float4 p = s_pts[t + u];
            float dd = fmaf(ax, p.x, p.w);
            dd = fmaf(ay, p.y, dd);
            dd = fmaf(az, p.z, dd);
            d[u] = dd;
        }
#pragma unroll
        for (int u = 0; u < 8; ++u) {
            const float dd = d[u];
            if (dd < s[15]) {
                // parallel sorted insert (descending j reads old s[j-1])
#pragma unroll
                for (int j = 15; j >= 1; --j)
                    s[j] = fminf(s[j], fmaxf(s[j - 1], dd));
                s[0] = fminf(s[0], dd);
                if (cnt < CAP) s_buf[cnt * 256 + tid] = (unsigned short)(t + u);
                ++cnt;
            }
        }
    }

    // Emission: exact tau filter over the collected superset; map to
    // original kv indices and original query row (unordered set downstream).
    const float tau = s[15];
    const unsigned* sx = g_sidx + (size_t)b * NKV;
    const int qorig = (int)g_qidx[(size_t)b * NQV + slot];
    unsigned* o = g_topk + ((size_t)b * NQV + qorig) * KNN;
    int out = 0;
    if (cnt <= CAP) {
        for (int i = 0; i < cnt && out < KNN; ++i) {
            const int idx = s_buf[i * 256 + tid];
            const float4 p = s_pts[idx];
            float dd = fmaf(ax, p.x, p.w);
            dd = fmaf(ay, p.y, dd);
            dd = fmaf(az, p.z, dd);
            if (dd <= tau) o[out++] = sx[idx];
        }
    } else {
        // ultra-rare overflow: exact rescan
        for (int t = 0; t < NKV && out < KNN; ++t) {
            const float4 p = s_pts[t];
            float dd = fmaf(ax, p.x, p.w);
            dd = fmaf(ay, p.y, dd);
            dd = fmaf(az, p.z, dd);
            if (dd <= tau) o[out++] = sx[t];
        }
    }
}

// ---------------------------------------------------------------------------
// Kernel A: projection GEMM (unchanged, known-good)
//   mode 0: W = w1[h][c]            -> g_kvproj, epilogue *= s1[h]
//   mode 1: W = w1[h][C+c]-w1[h][c] -> g_qterm,  epilogue = acc*s1[h] + t1[h]
// ---------------------------------------------------------------------------
__global__ __launch_bounds__(256) void proj_kernel(
    const float* __restrict__ feat, const float* __restrict__ w1,
    const float* __restrict__ g1, const float* __restrict__ b1,
    const float* __restrict__ m1, const float* __restrict__ v1, int mode)
{
    __shared__ float AsubT[32][132];
    __shared__ float WT[32][36];

    const int tid  = threadIdx.x;
    const int row0 = blockIdx.x * 128;
    const int h0   = (tid & 7) * 4;
    const int m0   = (tid >> 3) * 4;

    float acc[4][4];
#pragma unroll
    for (int i = 0; i < 4; ++i)
#pragma unroll
        for (int j = 0; j < 4; ++j) acc[i][j] = 0.0f;

    for (int k0 = 0; k0 < CC; k0 += 32) {
        {
            const int q4 = (tid & 7) * 4;
            const int r  = tid >> 3;
#pragma unroll
            for (int j = 0; j < 4; ++j) {
                const int row = r + j * 32;
                const float4 v = *(const float4*)(feat + (size_t)(row0 + row) * CC + k0 + q4);
                AsubT[q4 + 0][row] = v.x;
                AsubT[q4 + 1][row] = v.y;
                AsubT[q4 + 2][row] = v.z;
                AsubT[q4 + 3][row] = v.w;
            }
        }
        {
            const int kk = tid & 31;
            const int hb = tid >> 5;
#pragma unroll
            for (int j = 0; j < 4; ++j) {
                const int hh = hb + j * 8;
                float w = w1[hh * (2 * CC) + k0 + kk];
                if (mode) w = w1[hh * (2 * CC) + CC + k0 + kk] - w;
                WT[kk][hh] = w;
            }
        }
        __syncthreads();
#pragma unroll
        for (int kk = 0; kk < 32; ++kk) {
            const float4 a = *(const float4*)&AsubT[kk][m0];
            const float4 w = *(const float4*)&WT[kk][h0];
            const float av[4] = {a.x, a.y, a.z, a.w};
            const float wv[4] = {w.x, w.y, w.z, w.w};
#pragma unroll
            for (int i = 0; i < 4; ++i)
#pragma unroll
                for (int j = 0; j < 4; ++j)
                    acc[i][j] = fmaf(av[i], wv[j], acc[i][j]);
        }
        __syncthreads();
    }

    float sv[4], tv[4];
#pragma unroll
    for (int j = 0; j < 4; ++j) {
        const int h = h0 + j;
        const float sc = g1[h] * rsqrtf(v1[h] + EPSV);
        sv[j] = sc;
        tv[j] = mode ? (b1[h] - m1[h] * sc) : 0.0f;
    }
    float* out = mode ? g_qterm : g_kvproj;
#pragma unroll
    for (int i = 0; i < 4; ++i) {
        float4 o;
        o.x = fmaf(acc[i][0], sv[0], tv[0]);
        o.y = fmaf(acc[i][1], sv[1], tv[1]);
        o.z = fmaf(acc[i][2], sv[2], tv[2]);
        o.w = fmaf(acc[i][3], sv[3], tv[3]);
        *(float4*)(out + (size_t)(row0 + m0 + i) * HH + h0) = o;
    }
}

// ---------------------------------------------------------------------------
// Kernel C: gather + add + leaky + max over K, then y = max @ w2^T + BN2 + leaky
// ---------------------------------------------------------------------------
__global__ __launch_bounds__(512) void fuse_kernel(
    const float* __restrict__ w2, const float* __restrict__ g2,
    const float* __restrict__ b2, const float* __restrict__ m2,
    const float* __restrict__ v2, float* __restrict__ out)
{
    __shared__ float w2t[HH][260];    // transposed w2, padded
    __shared__ float smaxT[HH][68];   // [h][q_local]
    __shared__ float s2s[CC], t2s[CC];

    const int tid = threadIdx.x;

    for (int idx = tid; idx < CC * HH; idx += 512) {
        const int c = idx >> 5, h = idx & 31;
        w2t[h][c] = w2[idx];
    }
    if (tid < 256) {
        const float sc = g2[tid] * rsqrtf(v2[tid] + EPSV);
        s2s[tid] = sc;
        t2s[tid] = b2[tid] - m2[tid] * sc;
    }

    const int r0   = blockIdx.x * 64;
    const int b    = r0 >> 12;
    const int warp = tid >> 5, lane = tid & 31;
    const float* kvb = g_kvproj + (size_t)b * NKV * HH;

    for (int qi = warp * 4; qi < warp * 4 + 4; ++qi) {
        const int r = r0 + qi;
        const float qt = g_qterm[(size_t)r * HH + lane];
        const uint4* ip = (const uint4*)(g_topk + (size_t)r * KNN);
        const uint4 i0 = ip[0], i1 = ip[1], i2 = ip[2], i3 = ip[3];
        const unsigned id[16] = {i0.x, i0.y, i0.z, i0.w, i1.x, i1.y, i1.z, i1.w,
                                 i2.x, i2.y, i2.z, i2.w, i3.x, i3.y, i3.z, i3.w};
        float mx = -FINF;
#pragma unroll
        for (int k = 0; k < 16; ++k) {
            float v = kvb[(size_t)id[k] * HH + lane] + qt;
            v = fmaxf(v, 0.2f * v);  // leaky relu (slope < 1)
            mx = fmaxf(mx, v);
        }
        smaxT[lane][qi] = mx;
    }
    __syncthreads();

    const int q0 = (tid & 15) * 4;
    const int c0 = (tid >> 4) * 8;
    float acc[4][8];
#pragma unroll
    for (int i = 0; i < 4; ++i)
#pragma unroll
        for (int j = 0; j < 8; ++j) acc[i][j] = 0.0f;

#pragma unroll 8
    for (int kk = 0; kk < HH; ++kk) {
        const float4 a = *(const float4*)&smaxT[kk][q0];
        const float av[4] = {a.x, a.y, a.z, a.w};
        float bv[8];
        {
            const float4 t0 = *(const float4*)&w2t[kk][c0];
            const float4 t1 = *(const float4*)&w2t[kk][c0 + 4];
            bv[0] = t0.x; bv[1] = t0.y; bv[2] = t0.z; bv[3] = t0.w;
            bv[4] = t1.x; bv[5] = t1.y; bv[6] = t1.z; bv[7] = t1.w;
        }
#pragma unroll
        for (int i = 0; i < 4; ++i)
#pragma unroll
            for (int j = 0; j < 8; ++j)
                acc[i][j] = fmaf(av[i], bv[j], acc[i][j]);
    }

#pragma unroll
    for (int i = 0; i < 4; ++i) {
        const int r = r0 + q0 + i;
        float* op = out + (size_t)r * CC + c0;
#pragma unroll
        for (int j4 = 0; j4 < 2; ++j4) {
            float4 o;
            float y;
            y = fmaf(acc[i][j4 * 4 + 0], s2s[c0 + j4 * 4 + 0], t2s[c0 + j4 * 4 + 0]); o.x = fmaxf(y, 0.2f * y);
            y = fmaf(acc[i][j4 * 4 + 1], s2s[c0 + j4 * 4 + 1], t2s[c0 + j4 * 4 + 1]); o.y = fmaxf(y, 0.2f * y);
            y = fmaf(acc[i][j4 * 4 + 2], s2s[c0 + j4 * 4 + 2], t2s[c0 + j4 * 4 + 2]); o.z = fmaxf(y, 0.2f * y);
            y = fmaf(acc[i][j4 * 4 + 3], s2s[c0 + j4 * 4 + 3], t2s[c0 + j4 * 4 + 3]); o.w = fmaxf(y, 0.2f * y);
            *(float4*)(op + j4 * 4) = o;
        }
    }
}

// ---------------------------------------------------------------------------
extern "C" void kernel_launch(void* const* d_in, const int* in_sizes, int n_in,
                              void* d_out, int out_size)
{
    const float* qf   = (const float*)d_in[0];   // (8,4096,256)
    const float* qxyz = (const float*)d_in[1];   // (8,4096,3)
    const float* kvf  = (const float*)d_in[2];   // (8,4096,256)
    const float* kxyz = (const float*)d_in[3];   // (8,4096,3)
    const float* w1   = (const float*)d_in[4];   // (32,512)
    const float* g1   = (const float*)d_in[5];
    const float* b1   = (const float*)d_in[6];
    const float* m1   = (const float*)d_in[7];
    const float* v1   = (const float*)d_in[8];
    const float* w2   = (const float*)d_in[9];   // (256,32)
    const float* g2   = (const float*)d_in[10];
    const float* b2   = (const float*)d_in[11];
    const float* m2   = (const float*)d_in[12];
    const float* v2   = (const float*)d_in[13];
    float* out = (float*)d_out;

    const int smem_topk = 65536 + CAP * 256 * 2;   // 64KB pts + 80KB idx ring
    cudaFuncSetAttribute(topk_kernel, cudaFuncAttributeMaxDynamicSharedMemorySize, smem_topk);

    zero_kernel<<<(BB * NCELLM + 255) / 256, 256>>>();
    bin_kernel<<<128, 512>>>(kxyz, qxyz);
    scan_kernel<<<16, 1024>>>();
    scatter_kernel<<<128, 512>>>(kxyz, qxyz);
    topk_kernel<<<128, 256, smem_topk>>>();
    proj_kernel<<<256, 256>>>(kvf, w1, g1, b1, m1, v1, 0);
    proj_kernel<<<256, 256>>>(qf,  w1, g1, b1, m1, v1, 1);
    fuse_kernel<<<512, 512>>>(w2, g2, b2, m2, v2, out);
}

// round 10
// speedup vs baseline: 1.8028x; 1.8028x over previous
#include <cuda_runtime.h>

#define BB 8
#define NQV 4096
#define NKV 4096
#define CC 256
#define KNN 16
#define HH 32
#define EPSV 1e-5f
#define FINF 3.402823466e38f
#define CAP 160
#define TPB 128   // topk threads per block (2 blocks/SM: 104KB smem each)

// Scratch (device globals: allocation-free rule)
__device__ float    g_kvproj[BB * NKV * HH];   // s1 * (kv_feat @ w1a^T)
__device__ float    g_qterm [BB * NQV * HH];   // s1 * (q_feat @ (w1b-w1a)^T) + t1
__device__ unsigned g_topk  [BB * NQV * KNN];  // neighbor indices (unordered set)

// ---------------------------------------------------------------------------
// Kernel B: exact top-16 NN. One thread per query, full 4096-candidate stream
// in ORIGINAL (random) order -- optimal fire count for streaming top-k.
// Parallel sorted insert  s[j] = min(s[j], max(s[j-1], d))  (dep depth 2).
// Fired indices collected in a per-thread smem ring (superset of final 16);
// emission filters against exact tau in scan order. Overflow -> exact rescan.
// 128 threads/block, 256 blocks -> 2 blocks/SM, all 148 SMs covered.
// ---------------------------------------------------------------------------
extern "C" __global__ __launch_bounds__(TPB) void topk_kernel(
    const float* __restrict__ qxyz, const float* __restrict__ kxyz)
{
    extern __shared__ char smem_raw[];
    float4*         s_pts = (float4*)smem_raw;                   // 64KB
    unsigned short* s_buf = (unsigned short*)(smem_raw + 65536); // CAP*TPB*2 = 40KB

    const int tid = threadIdx.x;
    const int b   = blockIdx.x >> 5;               // 32 blocks per batch
    const int q   = b * NQV + (blockIdx.x & 31) * TPB + tid;

    // Stage all 4096 points of this batch (original order -> j == kv index)
    const float* kb = kxyz + (size_t)b * NKV * 3;
    for (int i = tid; i < NKV; i += TPB) {
        const float x = kb[i * 3 + 0];
        const float y = kb[i * 3 + 1];
        const float z = kb[i * 3 + 2];
        s_pts[i] = make_float4(x, y, z, x * x + y * y + z * z);
    }
    __syncthreads();

    const float qx = qxyz[(size_t)q * 3 + 0];
    const float qy = qxyz[(size_t)q * 3 + 1];
    const float qz = qxyz[(size_t)q * 3 + 2];
    const float ax = -2.0f * qx, ay = -2.0f * qy, az = -2.0f * qz;
    // ranking key d = |k|^2 - 2 q.k  (per-query constant |q|^2 dropped: exact)

    float s[16];
#pragma unroll
    for (int j = 0; j < 16; ++j) s[j] = FINF;
    int cnt = 0;

    for (int t = 0; t < NKV; t += 8) {
        float d[8];
#pragma unroll
        for (int u = 0; u < 8; ++u) {
            const float4 p = s_pts[t + u];
            float dd = fmaf(ax, p.x, p.w);
            dd = fmaf(ay, p.y, dd);
            dd = fmaf(az, p.z, dd);
            d[u] = dd;
        }
#pragma unroll
        for (int u = 0; u < 8; ++u) {
            const float dd = d[u];
            if (dd < s[15]) {
                // parallel sorted insert (descending j reads old s[j-1])
#pragma unroll
                for (int j = 15; j >= 1; --j)
                    s[j] = fminf(s[j], fmaxf(s[j - 1], dd));
                s[0] = fminf(s[0], dd);
                if (cnt < CAP) s_buf[cnt * TPB + tid] = (unsigned short)(t + u);
                ++cnt;
            }
        }
    }

    // Emission: exact tau filter over the collected superset, scan order.
    const float tau = s[15];
    unsigned* o = g_topk + (size_t)q * KNN;
    int out = 0;
    if (cnt <= CAP) {
        for (int i = 0; i < cnt && out < KNN; ++i) {
            const int idx = s_buf[i * TPB + tid];
            const float4 p = s_pts[idx];
            float dd = fmaf(ax, p.x, p.w);
            dd = fmaf(ay, p.y, dd);
            dd = fmaf(az, p.z, dd);
            if (dd <= tau) o[out++] = (unsigned)idx;
        }
    } else {
        // ultra-rare overflow: exact rescan
        for (int t = 0; t < NKV && out < KNN; ++t) {
            const float4 p = s_pts[t];
            float dd = fmaf(ax, p.x, p.w);
            dd = fmaf(ay, p.y, dd);
            dd = fmaf(az, p.z, dd);
            if (dd <= tau) o[out++] = (unsigned)t;
        }
    }
}

// ---------------------------------------------------------------------------
// Kernel A: projection GEMM (unchanged, known-good)
//   mode 0: W = w1[h][c]            -> g_kvproj, epilogue *= s1[h]
//   mode 1: W = w1[h][C+c]-w1[h][c] -> g_qterm,  epilogue = acc*s1[h] + t1[h]
// ---------------------------------------------------------------------------
__global__ __launch_bounds__(256) void proj_kernel(
    const float* __restrict__ feat, const float* __restrict__ w1,
    const float* __restrict__ g1, const float* __restrict__ b1,
    const float* __restrict__ m1, const float* __restrict__ v1, int mode)
{
    __shared__ float AsubT[32][132];
    __shared__ float WT[32][36];

    const int tid  = threadIdx.x;
    const int row0 = blockIdx.x * 128;
    const int h0   = (tid & 7) * 4;
    const int m0   = (tid >> 3) * 4;

    float acc[4][4];
#pragma unroll
    for (int i = 0; i < 4; ++i)
#pragma unroll
        for (int j = 0; j < 4; ++j) acc[i][j] = 0.0f;

    for (int k0 = 0; k0 < CC; k0 += 32) {
        {
            const int q4 = (tid & 7) * 4;
            const int r  = tid >> 3;
#pragma unroll
            for (int j = 0; j < 4; ++j) {
                const int row = r + j * 32;
                const float4 v = *(const float4*)(feat + (size_t)(row0 + row) * CC + k0 + q4);
                AsubT[q4 + 0][row] = v.x;
                AsubT[q4 + 1][row] = v.y;
                AsubT[q4 + 2][row] = v.z;
                AsubT[q4 + 3][row] = v.w;
            }
        }
        {
            const int kk = tid & 31;
            const int hb = tid >> 5;
#pragma unroll
            for (int j = 0; j < 4; ++j) {
                const int hh = hb + j * 8;
                float w = w1[hh * (2 * CC) + k0 + kk];
                if (mode) w = w1[hh * (2 * CC) + CC + k0 + kk] - w;
                WT[kk][hh] = w;
            }
        }
        __syncthreads();
#pragma unroll
        for (int kk = 0; kk < 32; ++kk) {
            const float4 a = *(const float4*)&AsubT[kk][m0];
            const float4 w = *(const float4*)&WT[kk][h0];
            const float av[4] = {a.x, a.y, a.z, a.w};
            const float wv[4] = {w.x, w.y, w.z, w.w};
#pragma unroll
            for (int i = 0; i < 4; ++i)
#pragma unroll
                for (int j = 0; j < 4; ++j)
                    acc[i][j] = fmaf(av[i], wv[j], acc[i][j]);
        }
        __syncthreads();
    }

    float sv[4], tv[4];
#pragma unroll
    for (int j = 0; j < 4; ++j) {
        const int h = h0 + j;
        const float sc = g1[h] * rsqrtf(v1[h] + EPSV);
        sv[j] = sc;
        tv[j] = mode ? (b1[h] - m1[h] * sc) : 0.0f;
    }
    float* out = mode ? g_qterm : g_kvproj;
#pragma unroll
    for (int i = 0; i < 4; ++i) {
        float4 o;
        o.x = fmaf(acc[i][0], sv[0], tv[0]);
        o.y = fmaf(acc[i][1], sv[1], tv[1]);
        o.z = fmaf(acc[i][2], sv[2], tv[2]);
        o.w = fmaf(acc[i][3], sv[3], tv[3]);
        *(float4*)(out + (size_t)(row0 + m0 + i) * HH + h0) = o;
    }
}

// ---------------------------------------------------------------------------
// Kernel C: gather + add + leaky + max over K, then y = max @ w2^T + BN2 + leaky
// 512 threads/block, 64 queries, acc[4][8].
// ---------------------------------------------------------------------------
__global__ __launch_bounds__(512) void fuse_kernel(
    const float* __restrict__ w2, const float* __restrict__ g2,
    const float* __restrict__ b2, const float* __restrict__ m2,
    const float* __restrict__ v2, float* __restrict__ out)
{
    __shared__ float w2t[HH][260];    // transposed w2, padded
    __shared__ float smaxT[HH][68];   // [h][q_local]
    __shared__ float s2s[CC], t2s[CC];

    const int tid = threadIdx.x;

    for (int idx = tid; idx < CC * HH; idx += 512) {
        const int c = idx >> 5, h = idx & 31;
        w2t[h][c] = w2[idx];
    }
    if (tid < 256) {
        const float sc = g2[tid] * rsqrtf(v2[tid] + EPSV);
        s2s[tid] = sc;
        t2s[tid] = b2[tid] - m2[tid] * sc;
    }

    const int r0   = blockIdx.x * 64;
    const int b    = r0 >> 12;
    const int warp = tid >> 5, lane = tid & 31;
    const float* kvb = g_kvproj + (size_t)b * NKV * HH;

    for (int qi = warp * 4; qi < warp * 4 + 4; ++qi) {
        const int r = r0 + qi;
        const float qt = g_qterm[(size_t)r * HH + lane];
        const uint4* ip = (const uint4*)(g_topk + (size_t)r * KNN);
        const uint4 i0 = ip[0], i1 = ip[1], i2 = ip[2], i3 = ip[3];
        const unsigned id[16] = {i0.x, i0.y, i0.z, i0.w, i1.x, i1.y, i1.z, i1.w,
                                 i2.x, i2.y, i2.z, i2.w, i3.x, i3.y, i3.z, i3.w};
        float mx = -FINF;
#pragma unroll
        for (int k = 0; k < 16; ++k) {
            float v = kvb[(size_t)id[k] * HH + lane] + qt;
            v = fmaxf(v, 0.2f * v);  // leaky relu (slope < 1)
            mx = fmaxf(mx, v);
        }
        smaxT[lane][qi] = mx;
    }
    __syncthreads();

    const int q0 = (tid & 15) * 4;
    const int c0 = (tid >> 4) * 8;
    float acc[4][8];
#pragma unroll
    for (int i = 0; i < 4; ++i)
#pragma unroll
        for (int j = 0; j < 8; ++j) acc[i][j] = 0.0f;

#pragma unroll 8
    for (int kk = 0; kk < HH; ++kk) {
        const float4 a = *(const float4*)&smaxT[kk][q0];
        const float av[4] = {a.x, a.y, a.z, a.w};
        float bv[8];
        {
            const float4 t0 = *(const float4*)&w2t[kk][c0];
            const float4 t1 = *(const float4*)&w2t[kk][c0 + 4];
            bv[0] = t0.x; bv[1] = t0.y; bv[2] = t0.z; bv[3] = t0.w;
            bv[4] = t1.x; bv[5] = t1.y; bv[6] = t1.z; bv[7] = t1.w;
        }
#pragma unroll
        for (int i = 0; i < 4; ++i)
#pragma unroll
            for (int j = 0; j < 8; ++j)
                acc[i][j] = fmaf(av[i], bv[j], acc[i][j]);
    }

#pragma unroll
    for (int i = 0; i < 4; ++i) {
        const int r = r0 + q0 + i;
        float* op = out + (size_t)r * CC + c0;
#pragma unroll
        for (int j4 = 0; j4 < 2; ++j4) {
            float4 o;
            float y;
            y = fmaf(acc[i][j4 * 4 + 0], s2s[c0 + j4 * 4 + 0], t2s[c0 + j4 * 4 + 0]); o.x = fmaxf(y, 0.2f * y);
            y = fmaf(acc[i][j4 * 4 + 1], s2s[c0 + j4 * 4 + 1], t2s[c0 + j4 * 4 + 1]); o.y = fmaxf(y, 0.2f * y);
            y = fmaf(acc[i][j4 * 4 + 2], s2s[c0 + j4 * 4 + 2], t2s[c0 + j4 * 4 + 2]); o.z = fmaxf(y, 0.2f * y);
            y = fmaf(acc[i][j4 * 4 + 3], s2s[c0 + j4 * 4 + 3], t2s[c0 + j4 * 4 + 3]); o.w = fmaxf(y, 0.2f * y);
            *(float4*)(op + j4 * 4) = o;
        }
    }
}

// ---------------------------------------------------------------------------
extern "C" void kernel_launch(void* const* d_in, const int* in_sizes, int n_in,
                              void* d_out, int out_size)
{
    const float* qf   = (const float*)d_in[0];   // (8,4096,256)
    const float* qxyz = (const float*)d_in[1];   // (8,4096,3)
    const float* kvf  = (const float*)d_in[2];   // (8,4096,256)
    const float* kxyz = (const float*)d_in[3];   // (8,4096,3)
    const float* w1   = (const float*)d_in[4];   // (32,512)
    const float* g1   = (const float*)d_in[5];
    const float* b1   = (const float*)d_in[6];
    const float* m1   = (const float*)d_in[7];
    const float* v1   = (const float*)d_in[8];
    const float* w2   = (const float*)d_in[9];   // (256,32)
    const float* g2   = (const float*)d_in[10];
    const float* b2   = (const float*)d_in[11];
    const float* m2   = (const float*)d_in[12];
    const float* v2   = (const float*)d_in[13];
    float* out = (float*)d_out;

    const int smem_topk = 65536 + CAP * TPB * 2;   // 64KB pts + 40KB idx ring
    cudaFuncSetAttribute(topk_kernel, cudaFuncAttributeMaxDynamicSharedMemorySize, smem_topk);

    topk_kernel<<<(BB * NQV) / TPB, TPB, smem_topk>>>(qxyz, kxyz);
    proj_kernel<<<256, 256>>>(kvf, w1, g1, b1, m1, v1, 0);
    proj_kernel<<<256, 256>>>(qf,  w1, g1, b1, m1, v1, 1);
    fuse_kernel<<<512, 512>>>(w2, g2, b2, m2, v2, out);
}

// round 11
// speedup vs baseline: 2.2606x; 1.2540x over previous
#include <cuda_runtime.h>

#define BB 8
#define NQV 4096
#define NKV 4096
#define CC 256
#define KNN 16
#define HH 32
#define EPSV 1e-5f
#define FINF 3.402823466e38f
#define FULLM 0xFFFFFFFFu

// Scratch (device globals: allocation-free rule)
__device__ float    g_kvproj[BB * NKV * HH];   // s1 * (kv_feat @ w1a^T)
__device__ float    g_qterm [BB * NQV * HH];   // s1 * (q_feat @ (w1b-w1a)^T) + t1
__device__ unsigned g_topk  [BB * NQV * KNN];  // neighbor indices
__device__ float4   g_pts   [BB * NKV];        // packed {x,y,z,|k|^2}

// ---------------------------------------------------------------------------
// Pack kv points once: {x,y,z,|k|^2} -> coalesced float4 array (L1-friendly).
// ---------------------------------------------------------------------------
__global__ void pack_kernel(const float* __restrict__ kxyz) {
    const int i = blockIdx.x * 512 + threadIdx.x;   // 64 x 512 = 32768
    const float x = kxyz[(size_t)i * 3 + 0];
    const float y = kxyz[(size_t)i * 3 + 1];
    const float z = kxyz[(size_t)i * 3 + 2];
    g_pts[i] = make_float4(x, y, z, x * x + y * y + z * z);
}

// ---------------------------------------------------------------------------
// Kernel B: exact top-16 NN. ONE QUERY PER WARP, max-occupancy (no smem).
// Lanes scan 32 candidates/step via coalesced __ldg (batch array L1-hot).
// Lane-distributed sorted list (lanes 0..15 hold (dist,idx), ascending);
// ballot -> per-fire parallel shift-insert (R3-validated logic & semantics:
// strict < keeps earliest index on ties, matching stable top_k).
// Ranking key d = |k|^2 - 2 q.k (per-query |q|^2 dropped: exact).
// 2048 blocks x 512 threads = 32768 warps -> 64 warps/SM; issue-bound.
// ---------------------------------------------------------------------------
extern "C" __global__ __launch_bounds__(512) void topk_kernel(
    const float* __restrict__ qxyz)
{
    const int q    = (blockIdx.x * 512 + threadIdx.x) >> 5;  // global warp id
    const int lane = threadIdx.x & 31;
    const int b    = q >> 12;

    const float qx = qxyz[(size_t)q * 3 + 0];
    const float qy = qxyz[(size_t)q * 3 + 1];
    const float qz = qxyz[(size_t)q * 3 + 2];
    const float ax = -2.0f * qx, ay = -2.0f * qy, az = -2.0f * qz;

    const float4* pts = g_pts + (size_t)b * NKV;

    float    s   = FINF;   // lane i (i<16): i-th smallest dist
    unsigned si  = 0;
    float    tau = FINF;   // broadcast copy of s@lane15

    for (int t = 0; t < NKV; t += 64) {
        // two batches in flight (MLP)
        const float4 p0 = __ldg(&pts[t + lane]);
        const float4 p1 = __ldg(&pts[t + 32 + lane]);
        float d0 = fmaf(ax, p0.x, p0.w);
        d0 = fmaf(ay, p0.y, d0);
        d0 = fmaf(az, p0.z, d0);
        float d1 = fmaf(ax, p1.x, p1.w);
        d1 = fmaf(ay, p1.y, d1);
        d1 = fmaf(az, p1.z, d1);

#pragma unroll
        for (int h = 0; h < 2; ++h) {
            const float d  = h ? d1 : d0;
            const int   tb = t + h * 32;
            unsigned m = __ballot_sync(FULLM, d < tau);
            while (m) {
                const int src = __ffs(m) - 1;
                m &= m - 1;
                const float dv = __shfl_sync(FULLM, d, src);
                if (dv < tau) {                      // warp-uniform branch
                    const unsigned iv = (unsigned)(tb + src);
                    float    s_up = __shfl_up_sync(FULLM, s, 1);
                    unsigned i_up = __shfl_up_sync(FULLM, si, 1);
                    if (lane == 0) s_up = -FINF;
                    if (s > dv) {
                        si = (s_up > dv) ? i_up : iv;
                        s  = fmaxf(s_up, dv);
                    }
                    tau = __shfl_sync(FULLM, s, 15);
                }
            }
        }
    }

    if (lane < KNN) g_topk[(size_t)q * KNN + lane] = si;
}

// ---------------------------------------------------------------------------
// Kernel A: projection GEMM (unchanged, known-good)
//   mode 0: W = w1[h][c]            -> g_kvproj, epilogue *= s1[h]
//   mode 1: W = w1[h][C+c]-w1[h][c] -> g_qterm,  epilogue = acc*s1[h] + t1[h]
// ---------------------------------------------------------------------------
__global__ __launch_bounds__(256) void proj_kernel(
    const float* __restrict__ feat, const float* __restrict__ w1,
    const float* __restrict__ g1, const float* __restrict__ b1,
    const float* __restrict__ m1, const float* __restrict__ v1, int mode)
{
    __shared__ float AsubT[32][132];
    __shared__ float WT[32][36];

    const int tid  = threadIdx.x;
    const int row0 = blockIdx.x * 128;
    const int h0   = (tid & 7) * 4;
    const int m0   = (tid >> 3) * 4;

    float acc[4][4];
#pragma unroll
    for (int i = 0; i < 4; ++i)
#pragma unroll
        for (int j = 0; j < 4; ++j) acc[i][j] = 0.0f;

    for (int k0 = 0; k0 < CC; k0 += 32) {
        {
            const int q4 = (tid & 7) * 4;
            const int r  = tid >> 3;
#pragma unroll
            for (int j = 0; j < 4; ++j) {
                const int row = r + j * 32;
                const float4 v = *(const float4*)(feat + (size_t)(row0 + row) * CC + k0 + q4);
                AsubT[q4 + 0][row] = v.x;
                AsubT[q4 + 1][row] = v.y;
                AsubT[q4 + 2][row] = v.z;
                AsubT[q4 + 3][row] = v.w;
            }
        }
        {
            const int kk = tid & 31;
            const int hb = tid >> 5;
#pragma unroll
            for (int j = 0; j < 4; ++j) {
                const int hh = hb + j * 8;
                float w = w1[hh * (2 * CC) + k0 + kk];
                if (mode) w = w1[hh * (2 * CC) + CC + k0 + kk] - w;
                WT[kk][hh] = w;
            }
        }
        __syncthreads();
#pragma unroll
        for (int kk = 0; kk < 32; ++kk) {
            const float4 a = *(const float4*)&AsubT[kk][m0];
            const float4 w = *(const float4*)&WT[kk][h0];
            const float av[4] = {a.x, a.y, a.z, a.w};
            const float wv[4] = {w.x, w.y, w.z, w.w};
#pragma unroll
            for (int i = 0; i < 4; ++i)
#pragma unroll
                for (int j = 0; j < 4; ++j)
                    acc[i][j] = fmaf(av[i], wv[j], acc[i][j]);
        }
        __syncthreads();
    }

    float sv[4], tv[4];
#pragma unroll
    for (int j = 0; j < 4; ++j) {
        const int h = h0 + j;
        const float sc = g1[h] * rsqrtf(v1[h] + EPSV);
        sv[j] = sc;
        tv[j] = mode ? (b1[h] - m1[h] * sc) : 0.0f;
    }
    float* out = mode ? g_qterm : g_kvproj;
#pragma unroll
    for (int i = 0; i < 4; ++i) {
        float4 o;
        o.x = fmaf(acc[i][0], sv[0], tv[0]);
        o.y = fmaf(acc[i][1], sv[1], tv[1]);
        o.z = fmaf(acc[i][2], sv[2], tv[2]);
        o.w = fmaf(acc[i][3], sv[3], tv[3]);
        *(float4*)(out + (size_t)(row0 + m0 + i) * HH + h0) = o;
    }
}

// ---------------------------------------------------------------------------
// Kernel C: gather + add + leaky + max over K, then y = max @ w2^T + BN2 + leaky
// 512 threads/block, 64 queries, acc[4][8].
// ---------------------------------------------------------------------------
__global__ __launch_bounds__(512) void fuse_kernel(
    const float* __restrict__ w2, const float* __restrict__ g2,
    const float* __restrict__ b2, const float* __restrict__ m2,
    const float* __restrict__ v2, float* __restrict__ out)
{
    __shared__ float w2t[HH][260];    // transposed w2, padded
    __shared__ float smaxT[HH][68];   // [h][q_local]
    __shared__ float s2s[CC], t2s[CC];

    const int tid = threadIdx.x;

    for (int idx = tid; idx < CC * HH; idx += 512) {
        const int c = idx >> 5, h = idx & 31;
        w2t[h][c] = w2[idx];
    }
    if (tid < 256) {
        const float sc = g2[tid] * rsqrtf(v2[tid] + EPSV);
        s2s[tid] = sc;
        t2s[tid] = b2[tid] - m2[tid] * sc;
    }

    const int r0   = blockIdx.x * 64;
    const int b    = r0 >> 12;
    const int warp = tid >> 5, lane = tid & 31;
    const float* kvb = g_kvproj + (size_t)b * NKV * HH;

    for (int qi = warp * 4; qi < warp * 4 + 4; ++qi) {
        const int r = r0 + qi;
        const float qt = g_qterm[(size_t)r * HH + lane];
        const uint4* ip = (const uint4*)(g_topk + (size_t)r * KNN);
        const uint4 i0 = ip[0], i1 = ip[1], i2 = ip[2], i3 = ip[3];
        const unsigned id[16] = {i0.x, i0.y, i0.z, i0.w, i1.x, i1.y, i1.z, i1.w,
                                 i2.x, i2.y, i2.z, i2.w, i3.x, i3.y, i3.z, i3.w};
        float mx = -FINF;
#pragma unroll
        for (int k = 0; k < 16; ++k) {
            float v = kvb[(size_t)id[k] * HH + lane] + qt;
            v = fmaxf(v, 0.2f * v);  // leaky relu (slope < 1)
            mx = fmaxf(mx, v);
        }
        smaxT[lane][qi] = mx;
    }
    __syncthreads();

    const int q0 = (tid & 15) * 4;
    const int c0 = (tid >> 4) * 8;
    float acc[4][8];
#pragma unroll
    for (int i = 0; i < 4; ++i)
#pragma unroll
        for (int j = 0; j < 8; ++j) acc[i][j] = 0.0f;

#pragma unroll 8
    for (int kk = 0; kk < HH; ++kk) {
        const float4 a = *(const float4*)&smaxT[kk][q0];
        const float av[4] = {a.x, a.y, a.z, a.w};
        float bv[8];
        {
            const float4 t0 = *(const float4*)&w2t[kk][c0];
            const float4 t1 = *(const float4*)&w2t[kk][c0 + 4];
            bv[0] = t0.x; bv[1] = t0.y; bv[2] = t0.z; bv[3] = t0.w;
            bv[4] = t1.x; bv[5] = t1.y; bv[6] = t1.z; bv[7] = t1.w;
        }
#pragma unroll
        for (int i = 0; i < 4; ++i)
#pragma unroll
            for (int j = 0; j < 8; ++j)
                acc[i][j] = fmaf(av[i], bv[j], acc[i][j]);
    }

#pragma unroll
    for (int i = 0; i < 4; ++i) {
        const int r = r0 + q0 + i;
        float* op = out + (size_t)r * CC + c0;
#pragma unroll
        for (int j4 = 0; j4 < 2; ++j4) {
            float4 o;
            float y;
            y = fmaf(acc[i][j4 * 4 + 0], s2s[c0 + j4 * 4 + 0], t2s[c0 + j4 * 4 + 0]); o.x = fmaxf(y, 0.2f * y);
            y = fmaf(acc[i][j4 * 4 + 1], s2s[c0 + j4 * 4 + 1], t2s[c0 + j4 * 4 + 1]); o.y = fmaxf(y, 0.2f * y);
            y = fmaf(acc[i][j4 * 4 + 2], s2s[c0 + j4 * 4 + 2], t2s[c0 + j4 * 4 + 2]); o.z = fmaxf(y, 0.2f * y);
            y = fmaf(acc[i][j4 * 4 + 3], s2s[c0 + j4 * 4 + 3], t2s[c0 + j4 * 4 + 3]); o.w = fmaxf(y, 0.2f * y);
            *(float4*)(op + j4 * 4) = o;
        }
    }
}

// ---------------------------------------------------------------------------
extern "C" void kernel_launch(void* const* d_in, const int* in_sizes, int n_in,
                              void* d_out, int out_size)
{
    const float* qf   = (const float*)d_in[0];   // (8,4096,256)
    const float* qxyz = (const float*)d_in[1];   // (8,4096,3)
    const float* kvf  = (const float*)d_in[2];   // (8,4096,256)
    const float* kxyz = (const float*)d_in[3];   // (8,4096,3)
    const float* w1   = (const float*)d_in[4];   // (32,512)
    const float* g1   = (const float*)d_in[5];
    const float* b1   = (const float*)d_in[6];
    const float* m1   = (const float*)d_in[7];
    const float* v1   = (const float*)d_in[8];
    const float* w2   = (const float*)d_in[9];   // (256,32)
    const float* g2   = (const float*)d_in[10];
    const float* b2   = (const float*)d_in[11];
    const float* m2   = (const float*)d_in[12];
    const float* v2   = (const float*)d_in[13];
    float* out = (float*)d_out;

    pack_kernel<<<64, 512>>>(kxyz);
    topk_kernel<<<2048, 512>>>(qxyz);
    proj_kernel<<<256, 256>>>(kvf, w1, g1, b1, m1, v1, 0);
    proj_kernel<<<256, 256>>>(qf,  w1, g1, b1, m1, v1, 1);
    fuse_kernel<<<512, 512>>>(w2, g2, b2, m2, v2, out);
}

// round 12
// speedup vs baseline: 2.3947x; 1.0593x over previous
#include <cuda_runtime.h>

#define BB 8
#define NQV 4096
#define NKV 4096
#define CC 256
#define KNN 16
#define HH 32
#define EPSV 1e-5f
#define FINF 3.402823466e38f
#define FULLM 0xFFFFFFFFu

// Scratch (device globals: allocation-free rule)
__device__ float    g_kvproj[BB * NKV * HH];   // s1 * (kv_feat @ w1a^T)
__device__ float    g_qterm [BB * NQV * HH];   // s1 * (q_feat @ (w1b-w1a)^T) + t1
__device__ unsigned g_topk  [BB * NQV * KNN];  // neighbor indices
__device__ float4   g_pts   [BB * NKV];        // packed {x,y,z,|k|^2}

// ---------------------------------------------------------------------------
// Pack kv points once: {x,y,z,|k|^2} -> coalesced float4 array (L1-friendly).
// ---------------------------------------------------------------------------
__global__ void pack_kernel(const float* __restrict__ kxyz) {
    const int i = blockIdx.x * 512 + threadIdx.x;   // 64 x 512 = 32768
    const float x = kxyz[(size_t)i * 3 + 0];
    const float y = kxyz[(size_t)i * 3 + 1];
    const float z = kxyz[(size_t)i * 3 + 2];
    g_pts[i] = make_float4(x, y, z, x * x + y * y + z * z);
}

// ---------------------------------------------------------------------------
// Kernel B: exact top-16 NN. TWO QUERIES PER WARP -- each 16B candidate load
// is amortized over 2 queries (halves L1 traffic, the measured floor).
// Lane-distributed sorted lists (lanes 0..15 hold (dist,idx) ascending),
// ballot -> parallel shift-insert; logic per query identical to the
// R3/R11-validated version (strict <, earliest index wins ties -> matches
// stable top_k). Ranking key d = |k|^2 - 2 q.k (|q|^2 dropped: exact).
// 1024 blocks x 512 threads = 16384 warps = 32768 queries.
// ---------------------------------------------------------------------------
extern "C" __global__ __launch_bounds__(512) void topk_kernel(
    const float* __restrict__ qxyz)
{
    const int w    = (blockIdx.x * 512 + threadIdx.x) >> 5;  // global warp id
    const int lane = threadIdx.x & 31;
    const int qa   = w * 2;                                  // queries qa, qa+1
    const int b    = qa >> 12;                               // same batch (even)

    const float aqx = qxyz[(size_t)qa * 3 + 0];
    const float aqy = qxyz[(size_t)qa * 3 + 1];
    const float aqz = qxyz[(size_t)qa * 3 + 2];
    const float bqx = qxyz[(size_t)(qa + 1) * 3 + 0];
    const float bqy = qxyz[(size_t)(qa + 1) * 3 + 1];
    const float bqz = qxyz[(size_t)(qa + 1) * 3 + 2];
    const float axa = -2.0f * aqx, aya = -2.0f * aqy, aza = -2.0f * aqz;
    const float axb = -2.0f * bqx, ayb = -2.0f * bqy, azb = -2.0f * bqz;

    const float4* pts = g_pts + (size_t)b * NKV;

    float    sa = FINF, sb = FINF;     // lane i (i<16): i-th smallest dist
    unsigned ia = 0,    ib = 0;
    float    taua = FINF, taub = FINF; // broadcast of s@lane15

    for (int t = 0; t < NKV; t += 64) {
        const float4 p0 = __ldg(&pts[t + lane]);
        const float4 p1 = __ldg(&pts[t + 32 + lane]);

        float da0 = fmaf(axa, p0.x, p0.w);
        da0 = fmaf(aya, p0.y, da0);
        da0 = fmaf(aza, p0.z, da0);
        float db0 = fmaf(axb, p0.x, p0.w);
        db0 = fmaf(ayb, p0.y, db0);
        db0 = fmaf(azb, p0.z, db0);
        float da1 = fmaf(axa, p1.x, p1.w);
        da1 = fmaf(aya, p1.y, da1);
        da1 = fmaf(aza, p1.z, da1);
        float db1 = fmaf(axb, p1.x, p1.w);
        db1 = fmaf(ayb, p1.y, db1);
        db1 = fmaf(azb, p1.z, db1);

#pragma unroll
        for (int h = 0; h < 2; ++h) {
            const float da = h ? da1 : da0;
            const float db = h ? db1 : db0;
            const int   tb = t + h * 32;

            unsigned ma = __ballot_sync(FULLM, da < taua);
            while (ma) {
                const int src = __ffs(ma) - 1;
                ma &= ma - 1;
                const float dv = __shfl_sync(FULLM, da, src);
                if (dv < taua) {
                    const unsigned iv = (unsigned)(tb + src);
                    float    s_up = __shfl_up_sync(FULLM, sa, 1);
                    unsigned i_up = __shfl_up_sync(FULLM, ia, 1);
                    if (lane == 0) s_up = -FINF;
                    if (sa > dv) {
                        ia = (s_up > dv) ? i_up : iv;
                        sa = fmaxf(s_up, dv);
                    }
                    taua = __shfl_sync(FULLM, sa, 15);
                }
            }
            unsigned mb = __ballot_sync(FULLM, db < taub);
            while (mb) {
                const int src = __ffs(mb) - 1;
                mb &= mb - 1;
                const float dv = __shfl_sync(FULLM, db, src);
                if (dv < taub) {
                    const unsigned iv = (unsigned)(tb + src);
                    float    s_up = __shfl_up_sync(FULLM, sb, 1);
                    unsigned i_up = __shfl_up_sync(FULLM, ib, 1);
                    if (lane == 0) s_up = -FINF;
                    if (sb > dv) {
                        ib = (s_up > dv) ? i_up : iv;
                        sb = fmaxf(s_up, dv);
                    }
                    taub = __shfl_sync(FULLM, sb, 15);
                }
            }
        }
    }

    if (lane < KNN) {
        g_topk[(size_t)qa * KNN + lane] = ia;
        g_topk[(size_t)(qa + 1) * KNN + lane] = ib;
    }
}

// ---------------------------------------------------------------------------
// Kernel A: projection GEMM, BOTH modes in one launch (mode = blockIdx.x>>8).
//   mode 0: W = w1[h][c]            -> g_kvproj, epilogue *= s1[h]
//   mode 1: W = w1[h][C+c]-w1[h][c] -> g_qterm,  epilogue = acc*s1[h] + t1[h]
// ---------------------------------------------------------------------------
__global__ __launch_bounds__(256) void proj_kernel(
    const float* __restrict__ kvf, const float* __restrict__ qf,
    const float* __restrict__ w1,
    const float* __restrict__ g1, const float* __restrict__ b1,
    const float* __restrict__ m1, const float* __restrict__ v1)
{
    __shared__ float AsubT[32][132];
    __shared__ float WT[32][36];

    const int tid  = threadIdx.x;
    const int mode = blockIdx.x >> 8;
    const float* feat = mode ? qf : kvf;
    const int row0 = (blockIdx.x & 255) * 128;
    const int h0   = (tid & 7) * 4;
    const int m0   = (tid >> 3) * 4;

    float acc[4][4];
#pragma unroll
    for (int i = 0; i < 4; ++i)
#pragma unroll
        for (int j = 0; j < 4; ++j) acc[i][j] = 0.0f;

    for (int k0 = 0; k0 < CC; k0 += 32) {
        {
            const int q4 = (tid & 7) * 4;
            const int r  = tid >> 3;
#pragma unroll
            for (int j = 0; j < 4; ++j) {
                const int row = r + j * 32;
                const float4 v = *(const float4*)(feat + (size_t)(row0 + row) * CC + k0 + q4);
                AsubT[q4 + 0][row] = v.x;
                AsubT[q4 + 1][row] = v.y;
                AsubT[q4 + 2][row] = v.z;
                AsubT[q4 + 3][row] = v.w;
            }
        }
        {
            const int kk = tid & 31;
            const int hb = tid >> 5;
#pragma unroll
            for (int j = 0; j < 4; ++j) {
                const int hh = hb + j * 8;
                float w = w1[hh * (2 * CC) + k0 + kk];
                if (mode) w = w1[hh * (2 * CC) + CC + k0 + kk] - w;
                WT[kk][hh] = w;
            }
        }
        __syncthreads();
#pragma unroll
        for (int kk = 0; kk < 32; ++kk) {
            const float4 a = *(const float4*)&AsubT[kk][m0];
            const float4 w = *(const float4*)&WT[kk][h0];
            const float av[4] = {a.x, a.y, a.z, a.w};
            const float wv[4] = {w.x, w.y, w.z, w.w};
#pragma unroll
            for (int i = 0; i < 4; ++i)
#pragma unroll
                for (int j = 0; j < 4; ++j)
                    acc[i][j] = fmaf(av[i], wv[j], acc[i][j]);
        }
        __syncthreads();
    }

    float sv[4], tv[4];
#pragma unroll
    for (int j = 0; j < 4; ++j) {
        const int h = h0 + j;
        const float sc = g1[h] * rsqrtf(v1[h] + EPSV);
        sv[j] = sc;
        tv[j] = mode ? (b1[h] - m1[h] * sc) : 0.0f;
    }
    float* out = mode ? g_qterm : g_kvproj;
#pragma unroll
    for (int i = 0; i < 4; ++i) {
        float4 o;
        o.x = fmaf(acc[i][0], sv[0], tv[0]);
        o.y = fmaf(acc[i][1], sv[1], tv[1]);
        o.z = fmaf(acc[i][2], sv[2], tv[2]);
        o.w = fmaf(acc[i][3], sv[3], tv[3]);
        *(float4*)(out + (size_t)(row0 + m0 + i) * HH + h0) = o;
    }
}

// ---------------------------------------------------------------------------
// Kernel C: gather + add + leaky + max over K, then y = max @ w2^T + BN2 + leaky
// 512 threads/block, 64 queries, acc[4][8].
// ---------------------------------------------------------------------------
__global__ __launch_bounds__(512) void fuse_kernel(
    const float* __restrict__ w2, const float* __restrict__ g2,
    const float* __restrict__ b2, const float* __restrict__ m2,
    const float* __restrict__ v2, float* __restrict__ out)
{
    __shared__ float w2t[HH][260];    // transposed w2, padded
    __shared__ float smaxT[HH][68];   // [h][q_local]
    __shared__ float s2s[CC], t2s[CC];

    const int tid = threadIdx.x;

    for (int idx = tid; idx < CC * HH; idx += 512) {
        const int c = idx >> 5, h = idx & 31;
        w2t[h][c] = w2[idx];
    }
    if (tid < 256) {
        const float sc = g2[tid] * rsqrtf(v2[tid] + EPSV);
        s2s[tid] = sc;
        t2s[tid] = b2[tid] - m2[tid] * sc;
    }

    const int r0   = blockIdx.x * 64;
    const int b    = r0 >> 12;
    const int warp = tid >> 5, lane = tid & 31;
    const float* kvb = g_kvproj + (size_t)b * NKV * HH;

    for (int qi = warp * 4; qi < warp * 4 + 4; ++qi) {
        const int r = r0 + qi;
        const float qt = g_qterm[(size_t)r * HH + lane];
        const uint4* ip = (const uint4*)(g_topk + (size_t)r * KNN);
        const uint4 i0 = ip[0], i1 = ip[1], i2 = ip[2], i3 = ip[3];
        const unsigned id[16] = {i0.x, i0.y, i0.z, i0.w, i1.x, i1.y, i1.z, i1.w,
                                 i2.x, i2.y, i2.z, i2.w, i3.x, i3.y, i3.z, i3.w};
        float mx = -FINF;
#pragma unroll
        for (int k = 0; k < 16; ++k) {
            float v = kvb[(size_t)id[k] * HH + lane] + qt;
            v = fmaxf(v, 0.2f * v);  // leaky relu (slope < 1)
            mx = fmaxf(mx, v);
        }
        smaxT[lane][qi] = mx;
    }
    __syncthreads();

    const int q0 = (tid & 15) * 4;
    const int c0 = (tid >> 4) * 8;
    float acc[4][8];
#pragma unroll
    for (int i = 0; i < 4; ++i)
#pragma unroll
        for (int j = 0; j < 8; ++j) acc[i][j] = 0.0f;

#pragma unroll 8
    for (int kk = 0; kk < HH; ++kk) {
        const float4 a = *(const float4*)&smaxT[kk][q0];
        const float av[4] = {a.x, a.y, a.z, a.w};
        float bv[8];
        {
            const float4 t0 = *(const float4*)&w2t[kk][c0];
            const float4 t1 = *(const float4*)&w2t[kk][c0 + 4];
            bv[0] = t0.x; bv[1] = t0.y; bv[2] = t0.z; bv[3] = t0.w;
            bv[4] = t1.x; bv[5] = t1.y; bv[6] = t1.z; bv[7] = t1.w;
        }
#pragma unroll
        for (int i = 0; i < 4; ++i)
#pragma unroll
            for (int j = 0; j < 8; ++j)
                acc[i][j] = fmaf(av[i], bv[j], acc[i][j]);
    }

#pragma unroll
    for (int i = 0; i < 4; ++i) {
        const int r = r0 + q0 + i;
        float* op = out + (size_t)r * CC + c0;
#pragma unroll
        for (int j4 = 0; j4 < 2; ++j4) {
            float4 o;
            float y;
            y = fmaf(acc[i][j4 * 4 + 0], s2s[c0 + j4 * 4 + 0], t2s[c0 + j4 * 4 + 0]); o.x = fmaxf(y, 0.2f * y);
            y = fmaf(acc[i][j4 * 4 + 1], s2s[c0 + j4 * 4 + 1], t2s[c0 + j4 * 4 + 1]); o.y = fmaxf(y, 0.2f * y);
            y = fmaf(acc[i][j4 * 4 + 2], s2s[c0 + j4 * 4 + 2], t2s[c0 + j4 * 4 + 2]); o.z = fmaxf(y, 0.2f * y);
            y = fmaf(acc[i][j4 * 4 + 3], s2s[c0 + j4 * 4 + 3], t2s[c0 + j4 * 4 + 3]); o.w = fmaxf(y, 0.2f * y);
            *(float4*)(op + j4 * 4) = o;
        }
    }
}

// ---------------------------------------------------------------------------
extern "C" void kernel_launch(void* const* d_in, const int* in_sizes, int n_in,
                              void* d_out, int out_size)
{
    const float* qf   = (const float*)d_in[0];   // (8,4096,256)
    const float* qxyz = (const float*)d_in[1];   // (8,4096,3)
    const float* kvf  = (const float*)d_in[2];   // (8,4096,256)
    const float* kxyz = (const float*)d_in[3];   // (8,4096,3)
    const float* w1   = (const float*)d_in[4];   // (32,512)
    const float* g1   = (const float*)d_in[5];
    const float* b1   = (const float*)d_in[6];
    const float* m1   = (const float*)d_in[7];
    const float* v1   = (const float*)d_in[8];
    const float* w2   = (const float*)d_in[9];   // (256,32)
    const float* g2   = (const float*)d_in[10];
    const float* b2   = (const float*)d_in[11];
    const float* m2   = (const float*)d_in[12];
    const float* v2   = (const float*)d_in[13];
    float* out = (float*)d_out;

    pack_kernel<<<64, 512>>>(kxyz);
    topk_kernel<<<1024, 512>>>(qxyz);
    proj_kernel<<<512, 256>>>(kvf, qf, w1, g1, b1, m1, v1);
    fuse_kernel<<<512, 512>>>(w2, g2, b2, m2, v2, out);
}